// round 10
// baseline (speedup 1.0000x reference)
#include <cuda_runtime.h>
#include <math.h>

#define NCTA 128
#define NTH  512
#define Bsz  256
#define Tlen 1024
#define Hdim 256
#define K2n  128   // Hdim/2 k-pairs (f32x2 lanes)
#define KG   8     // k-split groups
#define BT   64    // batch-threads per k-group (4 batches each)

// Persistent state, exchanged through L2 (double-buffered by step parity).
// u64 layout: [k2][b] packs {h[2k2][b], h[2k2+1][b]}.
__device__ unsigned long long g_h0p[2][K2n * Bsz];
__device__ unsigned long long g_h1p[2][K2n * Bsz];
__device__ float g_xT[Tlen * Bsz];   // x transposed: [t][b]
__device__ unsigned g_cntA = 0;      // barrier line A (h0 publishes)
__device__ unsigned g_cntB = 0;      // barrier line B (h1 publishes)
__device__ unsigned g_done = 0;      // end-of-kernel reset rendezvous

union F2U { float2 f; unsigned long long u; };

__device__ __forceinline__ unsigned long long pack2(float a, float b) {
    F2U v; v.f.x = a; v.f.y = b; return v.u;
}
__device__ __forceinline__ float2 unpack2(unsigned long long u) {
    F2U v; v.u = u; return v.f;
}
// Blackwell packed fp32x2 FMA: 2 exact fp32 MACs per instruction.
__device__ __forceinline__ unsigned long long ffma2(unsigned long long a,
                                                    unsigned long long b,
                                                    unsigned long long c) {
    unsigned long long d;
    asm("fma.rn.f32x2 %0, %1, %2, %3;" : "=l"(d) : "l"(a), "l"(b), "l"(c));
    return d;
}
__device__ __forceinline__ float redsum(unsigned long long a) {
    float2 v = unpack2(a); return v.x + v.y;
}
__device__ __forceinline__ float sigf(float x) {
    return __fdividef(1.0f, 1.0f + __expf(-x));
}
__device__ __forceinline__ float tanhf_(float x) {
    return fmaf(2.0f, sigf(2.0f * x), -1.0f);
}

// Split-phase grid barrier (NCTA co-resident CTAs, 1/SM).
__device__ __forceinline__ void bar_arrive(unsigned* c) {
    __syncthreads();                       // CTA's stores done
    if (threadIdx.x == 0) { __threadfence(); atomicAdd(c, 1u); }
}
__device__ __forceinline__ void bar_wait(unsigned* c, unsigned target) {
    if (threadIdx.x == 0) {
        unsigned v;
        do {
            asm volatile("ld.acquire.gpu.u32 %0, [%1];" : "=r"(v) : "l"(c));
        } while (v < target);
    }
    __syncthreads();
}

// ---- matvec slice: N k2-pairs, 8 row-u64 weights, 4 batches per thread ----
// acc[w][b]: w = q*2 + j (gate q, unit j), b in [0,4).
// hp points at [k2=0..N)[batch base], stride Bsz; sW at 4 ulonglong2 per k2.
template<int N>
__device__ __forceinline__ void mv_acc(const unsigned long long* __restrict__ hp,
                                       const ulonglong2* __restrict__ sW,
                                       unsigned long long acc[8][4]) {
    unsigned long long h[4];
    #pragma unroll
    for (int b = 0; b < 4; ++b) h[b] = __ldcg(hp + b);
    #pragma unroll 4
    for (int i = 0; i < N; ++i) {
        unsigned long long hn[4];
        if (i + 1 < N) {
            #pragma unroll
            for (int b = 0; b < 4; ++b)
                hn[b] = __ldcg(hp + (i + 1) * Bsz + b);
        }
        #pragma unroll
        for (int q = 0; q < 4; ++q) {
            ulonglong2 w = sW[i * 4 + q];            // broadcast LDS.128
            #pragma unroll
            for (int b = 0; b < 4; ++b) {
                acc[q * 2 + 0][b] = ffma2(h[b], w.x, acc[q * 2 + 0][b]);
                acc[q * 2 + 1][b] = ffma2(h[b], w.y, acc[q * 2 + 1][b]);
            }
        }
        if (i + 1 < N) {
            #pragma unroll
            for (int b = 0; b < 4; ++b) h[b] = hn[b];
        }
    }
}

// write partials: sRedF[(kg*8 + w)*Bsz + b4 .. +3] as float4
__device__ __forceinline__ void wr_part(float4* __restrict__ sRed4,
                                        unsigned long long acc[8][4],
                                        int kg, int bt) {
    #pragma unroll
    for (int w = 0; w < 8; ++w)
        sRed4[(kg * 8 + w) * BT + bt] =
            make_float4(redsum(acc[w][0]), redsum(acc[w][1]),
                        redsum(acc[w][2]), redsum(acc[w][3]));
}

__global__ void __launch_bounds__(NTH, 1)
lstm_fused(const float* __restrict__ x,
           const float* __restrict__ Wih0, const float* __restrict__ Whh0,
           const float* __restrict__ bih0, const float* __restrict__ bhh0,
           const float* __restrict__ Wih1, const float* __restrict__ Whh1,
           const float* __restrict__ bih1, const float* __restrict__ bhh1,
           const float* __restrict__ Wlin, const float* __restrict__ blin,
           float* __restrict__ out)
{
    // sW0[k2*4+q]: .x = {W[q*H+u0][2k2..+1]}, .y = unit u0+1 (pair-packed)
    __shared__ ulonglong2 sW0[K2n * 4];          // 8 KB  Whh0
    __shared__ ulonglong2 sW1[2 * K2n * 4];      // 16 KB [Wih1 | Whh1] concat
    __shared__ float4 sRed4[KG * 8 * BT];        // 64 KB partials [kg][w][bt]
    __shared__ float sWx[8], sB0[8], sB1[8];     // per-CTA gate consts [q*2+j]
    __shared__ float sWlin[Hdim];
    __shared__ float sOut[8];

    const int tid = threadIdx.x;
    const int bt  = tid & (BT - 1);        // batch-thread 0..63
    const int kg  = tid >> 6;              // k-group 0..7 (warp-uniform)
    const int b4  = bt * 4;                // batches b4..b4+3
    const int cta = blockIdx.x;
    const int u0  = 2 * cta;               // owned unit pair (both layers)

    // activation role (all 512 threads): unit aj, batch ab
    const int aj  = tid >> 8;              // 0..1
    const int ab  = tid & 255;

    const float* sRedF = (const float*)sRed4;    // [(kg*8 + w)*Bsz + b]

    // ---- one-time staging ----
    for (int i = cta * NTH + tid; i < Bsz * Tlen; i += NCTA * NTH) {
        int bb = i >> 10, t = i & (Tlen - 1);
        g_xT[t * Bsz + bb] = x[i];
    }
    for (int e = tid; e < K2n * 4; e += NTH) {
        int k2 = e >> 2, q = e & 3;
        int base = (q * Hdim + u0) * Hdim + 2 * k2;
        sW0[e] = make_ulonglong2(pack2(Whh0[base],        Whh0[base + 1]),
                                 pack2(Whh0[base + Hdim], Whh0[base + Hdim + 1]));
    }
    for (int e = tid; e < 2 * K2n * 4; e += NTH) {
        int k2p = e >> 2, q = e & 3;
        const float* W = (k2p < K2n) ? Wih1 : Whh1;
        int k2 = k2p & (K2n - 1);
        int base = (q * Hdim + u0) * Hdim + 2 * k2;
        sW1[e] = make_ulonglong2(pack2(W[base],        W[base + 1]),
                                 pack2(W[base + Hdim], W[base + Hdim + 1]));
    }
    if (tid < 8) {
        int q = tid >> 1, j = tid & 1;
        int g = q * Hdim + u0 + j;
        sWx[tid] = Wih0[g];                // input dim == 1
        sB0[tid] = bih0[g] + bhh0[g];
        sB1[tid] = bih1[g] + bhh1[g];
    }
    if (tid < Hdim) sWlin[tid] = Wlin[tid];
    const float bl = __ldg(blin);

    if (tid < Bsz) {                       // zero initial state (parity-0)
        g_h0p[0][cta * Bsz + tid] = 0ull;
        g_h1p[0][cta * Bsz + tid] = 0ull;
    }
    float c0 = 0.f, c1 = 0.f;              // cell state for (aj, ab)

    // init barrier (line A): staging + zeros visible
    bar_arrive(&g_cntA);
    bar_wait(&g_cntA, 1u * NCTA);

    unsigned long long acc[8][4];

    // ---- prologue: L0(0): h0p[0] -> h0p[1] ----
    {
        #pragma unroll
        for (int w = 0; w < 8; ++w)
            #pragma unroll
            for (int b = 0; b < 4; ++b) acc[w][b] = 0ull;
        mv_acc<16>(g_h0p[0] + (kg * 16) * Bsz + b4, sW0 + (kg * 16) * 4, acc);
        wr_part(sRed4, acc, kg, bt);
        __syncthreads();
        float gi = 0.f, gf = 0.f, gg = 0.f, go = 0.f;
        #pragma unroll
        for (int g = 0; g < KG; ++g) {
            gi += sRedF[(g * 8 + 0 * 2 + aj) * Bsz + ab];
            gf += sRedF[(g * 8 + 1 * 2 + aj) * Bsz + ab];
            gg += sRedF[(g * 8 + 2 * 2 + aj) * Bsz + ab];
            go += sRedF[(g * 8 + 3 * 2 + aj) * Bsz + ab];
        }
        float xv = g_xT[0 * Bsz + ab];
        gi += fmaf(sWx[0 * 2 + aj], xv, sB0[0 * 2 + aj]);
        gf += fmaf(sWx[1 * 2 + aj], xv, sB0[1 * 2 + aj]);
        gg += fmaf(sWx[2 * 2 + aj], xv, sB0[2 * 2 + aj]);
        go += fmaf(sWx[3 * 2 + aj], xv, sB0[3 * 2 + aj]);
        float cn = sigf(gf) * c0 + sigf(gi) * tanhf_(gg);
        c0 = cn;
        ((float*)g_h0p[1])[(cta * Bsz + ab) * 2 + aj] = sigf(go) * tanhf_(cn);
        bar_arrive(&g_cntA);
        bar_wait(&g_cntA, 2u * NCTA);
    }

    for (int t = 0; t < Tlen; ++t) {
        const int pr = t & 1, nx = pr ^ 1;

        // ---- L1(t): h0p[nx] (new) + h1p[pr] -> h1p[nx] ----
        {
            #pragma unroll
            for (int w = 0; w < 8; ++w)
                #pragma unroll
                for (int b = 0; b < 4; ++b) acc[w][b] = 0ull;
            // warp-uniform source: kg 0-3 -> h0_new (Wih1), kg 4-7 -> h1_prev (Whh1)
            const unsigned long long* hs = (kg < 4) ? g_h0p[nx] : g_h1p[pr];
            const int kh0 = (kg & 3) * 32;             // h k2 base
            mv_acc<32>(hs + kh0 * Bsz + b4, sW1 + (kg * 32) * 4, acc);
            wr_part(sRed4, acc, kg, bt);
            __syncthreads();
            float gi = sB1[0 * 2 + aj], gf = sB1[1 * 2 + aj];
            float gg = sB1[2 * 2 + aj], go = sB1[3 * 2 + aj];
            #pragma unroll
            for (int g = 0; g < KG; ++g) {
                gi += sRedF[(g * 8 + 0 * 2 + aj) * Bsz + ab];
                gf += sRedF[(g * 8 + 1 * 2 + aj) * Bsz + ab];
                gg += sRedF[(g * 8 + 2 * 2 + aj) * Bsz + ab];
                go += sRedF[(g * 8 + 3 * 2 + aj) * Bsz + ab];
            }
            float cn = sigf(gf) * c1 + sigf(gi) * tanhf_(gg);
            c1 = cn;
            ((float*)g_h1p[nx])[(cta * Bsz + ab) * 2 + aj] = sigf(go) * tanhf_(cn);
        }
        bar_arrive(&g_cntB);                 // idB = t+1

        // ---- L0(t+1): h0p[nx] -> h0p[pr]  (hides B-barrier latency) ----
        if (t < Tlen - 1) {
            #pragma unroll
            for (int w = 0; w < 8; ++w)
                #pragma unroll
                for (int b = 0; b < 4; ++b) acc[w][b] = 0ull;
            mv_acc<16>(g_h0p[nx] + (kg * 16) * Bsz + b4, sW0 + (kg * 16) * 4, acc);
            wr_part(sRed4, acc, kg, bt);
            __syncthreads();
            float gi = 0.f, gf = 0.f, gg = 0.f, go = 0.f;
            #pragma unroll
            for (int g = 0; g < KG; ++g) {
                gi += sRedF[(g * 8 + 0 * 2 + aj) * Bsz + ab];
                gf += sRedF[(g * 8 + 1 * 2 + aj) * Bsz + ab];
                gg += sRedF[(g * 8 + 2 * 2 + aj) * Bsz + ab];
                go += sRedF[(g * 8 + 3 * 2 + aj) * Bsz + ab];
            }
            float xv = g_xT[(t + 1) * Bsz + ab];
            gi += fmaf(sWx[0 * 2 + aj], xv, sB0[0 * 2 + aj]);
            gf += fmaf(sWx[1 * 2 + aj], xv, sB0[1 * 2 + aj]);
            gg += fmaf(sWx[2 * 2 + aj], xv, sB0[2 * 2 + aj]);
            go += fmaf(sWx[3 * 2 + aj], xv, sB0[3 * 2 + aj]);
            float cn = sigf(gf) * c0 + sigf(gi) * tanhf_(gg);
            c0 = cn;
            ((float*)g_h0p[pr])[(cta * Bsz + ab) * 2 + aj] = sigf(go) * tanhf_(cn);
            bar_arrive(&g_cntA);             // idA = t+3
        }

        // ---- wait for all h1(t), then output dot for batches {u0, u0+1} ----
        bar_wait(&g_cntB, (unsigned)(t + 1) * NCTA);
        {
            if (tid < 256) {
                const unsigned long long* __restrict__ hc = g_h1p[nx];
                int half = tid >> 7;         // 0..127 -> batch u0, 128..255 -> u0+1
                int kk   = tid & 127;
                int bb   = u0 + half;
                float2 hv = unpack2(__ldcg(hc + kk * Bsz + bb));
                float part = hv.x * sWlin[2 * kk] + hv.y * sWlin[2 * kk + 1];
                #pragma unroll
                for (int off = 16; off > 0; off >>= 1)
                    part += __shfl_down_sync(0xffffffffu, part, off);
                if ((tid & 31) == 0) sOut[tid >> 5] = part;
            }
            __syncthreads();
            if (tid == 0) {
                out[(u0 + 0) * Tlen + t] = sOut[0] + sOut[1] + sOut[2] + sOut[3] + bl;
                out[(u0 + 1) * Tlen + t] = sOut[4] + sOut[5] + sOut[6] + sOut[7] + bl;
            }
        }

        if (t < Tlen - 1)
            bar_wait(&g_cntA, (unsigned)(t + 3) * NCTA);   // h0(t+1) visible
    }

    // reset counters for next launch
    __syncthreads();
    if (tid == 0) {
        __threadfence();
        unsigned old = atomicAdd(&g_done, 1u);
        if (old == NCTA - 1) {
            atomicExch(&g_cntA, 0u);
            atomicExch(&g_cntB, 0u);
            atomicExch(&g_done, 0u);
        }
    }
}

extern "C" void kernel_launch(void* const* d_in, const int* in_sizes, int n_in,
                              void* d_out, int out_size) {
    (void)in_sizes; (void)n_in; (void)out_size;
    lstm_fused<<<NCTA, NTH>>>(
        (const float*)d_in[0],
        (const float*)d_in[1], (const float*)d_in[2],
        (const float*)d_in[3], (const float*)d_in[4],
        (const float*)d_in[5], (const float*)d_in[6],
        (const float*)d_in[7], (const float*)d_in[8],
        (const float*)d_in[9], (const float*)d_in[10],
        (float*)d_out);
}

// round 11
// speedup vs baseline: 2.1033x; 2.1033x over previous
#include <cuda_runtime.h>
#include <math.h>

#define NCTA 128
#define NTH  512
#define Bsz  256
#define Tlen 1024
#define Hdim 256
#define K2n  128   // Hdim/2 k-pairs (f32x2 lanes)
#define K2PT 32    // K2n / 4 k-split groups

// Persistent state, exchanged through L2 (double-buffered by step parity).
// u64 layout: [k2][b] packs {h[2k2][b], h[2k2+1][b]}.
__device__ unsigned long long g_h0p[2][K2n * Bsz];
__device__ unsigned long long g_h1p[2][K2n * Bsz];
__device__ float g_xT[Tlen * Bsz];   // x transposed: [t][b]
__device__ unsigned g_cntA = 0;      // barrier line A (h0 publishes)
__device__ unsigned g_cntB = 0;      // barrier line B (h1 publishes)
__device__ unsigned g_done = 0;      // end-of-kernel reset rendezvous

union F2U { float2 f; unsigned long long u; };

__device__ __forceinline__ unsigned long long pack2(float a, float b) {
    F2U v; v.f.x = a; v.f.y = b; return v.u;
}
__device__ __forceinline__ float2 unpack2(unsigned long long u) {
    F2U v; v.u = u; return v.f;
}
// Blackwell packed fp32x2 FMA: 2 exact fp32 MACs per instruction.
__device__ __forceinline__ unsigned long long ffma2(unsigned long long a,
                                                    unsigned long long b,
                                                    unsigned long long c) {
    unsigned long long d;
    asm("fma.rn.f32x2 %0, %1, %2, %3;" : "=l"(d) : "l"(a), "l"(b), "l"(c));
    return d;
}
__device__ __forceinline__ float redsum(unsigned long long a) {
    float2 v = unpack2(a); return v.x + v.y;
}
__device__ __forceinline__ float sigf(float x) {
    return __fdividef(1.0f, 1.0f + __expf(-x));
}
__device__ __forceinline__ float tanhf_(float x) {
    return fmaf(2.0f, sigf(2.0f * x), -1.0f);
}

// Split-phase grid barrier (NCTA co-resident CTAs, 1/SM).
// Publish with a release-annotated reduction: orders all prior stores without
// a standalone MEMBAR.GPU on the critical path.
__device__ __forceinline__ void bar_arrive(unsigned* c) {
    __syncthreads();                       // CTA's stores done
    if (threadIdx.x == 0) {
        asm volatile("red.release.gpu.global.add.u32 [%0], %1;"
                     :: "l"(c), "r"(1u) : "memory");
    }
}
__device__ __forceinline__ void bar_wait(unsigned* c, unsigned target) {
    if (threadIdx.x == 0) {
        unsigned v;
        do {
            asm volatile("ld.acquire.gpu.u32 %0, [%1];" : "=r"(v) : "l"(c));
        } while (v < target);
    }
    __syncthreads();
}

// ---- layer-0 matvec slice + one-round k reduction ----
__device__ __forceinline__ void mv_l0(const unsigned long long* __restrict__ hp,
                                      const ulonglong2* __restrict__ sW,
                                      float4* __restrict__ sRed,
                                      int b2, int ks, int k0) {
    unsigned long long aA[4][2], aB[4][2];
    #pragma unroll
    for (int q = 0; q < 4; ++q) { aA[q][0]=0ull; aA[q][1]=0ull; aB[q][0]=0ull; aB[q][1]=0ull; }
    #pragma unroll 16
    for (int i = 0; i < K2PT; ++i) {
        int k2 = k0 + i;
        unsigned long long hA = __ldcg(hp + k2 * Bsz + b2);
        unsigned long long hB = __ldcg(hp + k2 * Bsz + b2 + 128);
        #pragma unroll
        for (int q = 0; q < 4; ++q) {
            ulonglong2 w = sW[k2 * 4 + q];           // broadcast LDS.128
            aA[q][0] = ffma2(hA, w.x, aA[q][0]);
            aA[q][1] = ffma2(hA, w.y, aA[q][1]);
            aB[q][0] = ffma2(hB, w.x, aB[q][0]);
            aB[q][1] = ffma2(hB, w.y, aB[q][1]);
        }
    }
    #pragma unroll
    for (int jj = 0; jj < 2; ++jj) {
        sRed[(ks*4 + jj*2 + 0)*128 + b2] =
            make_float4(redsum(aA[0][jj]), redsum(aA[1][jj]),
                        redsum(aA[2][jj]), redsum(aA[3][jj]));
        sRed[(ks*4 + jj*2 + 1)*128 + b2] =
            make_float4(redsum(aB[0][jj]), redsum(aB[1][jj]),
                        redsum(aB[2][jj]), redsum(aB[3][jj]));
    }
    __syncthreads();
}

// ---- layer-1 matvec slice (two input matrices) + one-round reduction ----
__device__ __forceinline__ void mv_l1(const unsigned long long* __restrict__ ha,
                                      const unsigned long long* __restrict__ hb,
                                      const ulonglong2* __restrict__ sWi,
                                      const ulonglong2* __restrict__ sWh,
                                      float4* __restrict__ sRed,
                                      int b2, int ks, int k0) {
    unsigned long long aA[4][2], aB[4][2];
    #pragma unroll
    for (int q = 0; q < 4; ++q) { aA[q][0]=0ull; aA[q][1]=0ull; aB[q][0]=0ull; aB[q][1]=0ull; }
    #pragma unroll 8
    for (int i = 0; i < K2PT; ++i) {
        int k2 = k0 + i;
        unsigned long long vaA = __ldcg(ha + k2 * Bsz + b2);
        unsigned long long vaB = __ldcg(ha + k2 * Bsz + b2 + 128);
        unsigned long long vbA = __ldcg(hb + k2 * Bsz + b2);
        unsigned long long vbB = __ldcg(hb + k2 * Bsz + b2 + 128);
        #pragma unroll
        for (int q = 0; q < 4; ++q) {
            ulonglong2 wi = sWi[k2 * 4 + q];
            ulonglong2 wh = sWh[k2 * 4 + q];
            aA[q][0] = ffma2(vaA, wi.x, aA[q][0]);
            aA[q][1] = ffma2(vaA, wi.y, aA[q][1]);
            aB[q][0] = ffma2(vaB, wi.x, aB[q][0]);
            aB[q][1] = ffma2(vaB, wi.y, aB[q][1]);
            aA[q][0] = ffma2(vbA, wh.x, aA[q][0]);
            aA[q][1] = ffma2(vbA, wh.y, aA[q][1]);
            aB[q][0] = ffma2(vbB, wh.x, aB[q][0]);
            aB[q][1] = ffma2(vbB, wh.y, aB[q][1]);
        }
    }
    #pragma unroll
    for (int jj = 0; jj < 2; ++jj) {
        sRed[(ks*4 + jj*2 + 0)*128 + b2] =
            make_float4(redsum(aA[0][jj]), redsum(aA[1][jj]),
                        redsum(aA[2][jj]), redsum(aA[3][jj]));
        sRed[(ks*4 + jj*2 + 1)*128 + b2] =
            make_float4(redsum(aB[0][jj]), redsum(aB[1][jj]),
                        redsum(aB[2][jj]), redsum(aB[3][jj]));
    }
    __syncthreads();
}

// gather this thread's (j,m) gate sums from the 4 k-group partials
__device__ __forceinline__ float4 red_gather(const float4* __restrict__ sRed,
                                             int ks, int b2) {
    float4 s = sRed[(0*4 + ks)*128 + b2];
    #pragma unroll
    for (int g = 1; g < 4; ++g) {
        float4 v = sRed[(g*4 + ks)*128 + b2];
        s.x += v.x; s.y += v.y; s.z += v.z; s.w += v.w;
    }
    return s;
}

__global__ void __launch_bounds__(NTH, 1)
lstm_fused(const float* __restrict__ x,
           const float* __restrict__ Wih0, const float* __restrict__ Whh0,
           const float* __restrict__ bih0, const float* __restrict__ bhh0,
           const float* __restrict__ Wih1, const float* __restrict__ Whh1,
           const float* __restrict__ bih1, const float* __restrict__ bhh1,
           const float* __restrict__ Wlin, const float* __restrict__ blin,
           float* __restrict__ out)
{
    __shared__ ulonglong2 sW0 [K2n * 4];   // 8 KB each, pair-packed
    __shared__ ulonglong2 sW1i[K2n * 4];
    __shared__ ulonglong2 sW1h[K2n * 4];
    __shared__ float4 sRed[16 * 128];      // 32 KB one-round reduction buffer
    __shared__ float sWx[8], sB0[8], sB1[8];
    __shared__ float sWlin[Hdim];
    __shared__ float sOut[8];

    const int tid = threadIdx.x;
    const int b2  = tid & 127;
    const int ks  = tid >> 7;              // 0..3 (warp-uniform)
    const int cta = blockIdx.x;
    const int u0  = 2 * cta;
    const int jmu = ks >> 1;               // unit-in-pair this thread activates
    const int mmu = ks & 1;                // batch-half this thread activates
    const int bown = b2 + mmu * 128;       // owned batch index
    const int k0  = ks * K2PT;

    // ---- one-time staging ----
    for (int i = cta * NTH + tid; i < Bsz * Tlen; i += NCTA * NTH) {
        int b = i >> 10, t = i & (Tlen - 1);
        g_xT[t * Bsz + b] = x[i];
    }
    for (int e = tid; e < K2n * 4; e += NTH) {
        int k2 = e >> 2, q = e & 3;
        int base = (q * Hdim + u0) * Hdim + 2 * k2;
        sW0[e]  = make_ulonglong2(pack2(Whh0[base],        Whh0[base + 1]),
                                  pack2(Whh0[base + Hdim], Whh0[base + Hdim + 1]));
        sW1i[e] = make_ulonglong2(pack2(Wih1[base],        Wih1[base + 1]),
                                  pack2(Wih1[base + Hdim], Wih1[base + Hdim + 1]));
        sW1h[e] = make_ulonglong2(pack2(Whh1[base],        Whh1[base + 1]),
                                  pack2(Whh1[base + Hdim], Whh1[base + Hdim + 1]));
    }
    if (tid < 8) {
        int q = tid >> 1, j = tid & 1;
        int g = q * Hdim + u0 + j;
        sWx[tid] = Wih0[g];
        sB0[tid] = bih0[g] + bhh0[g];
        sB1[tid] = bih1[g] + bhh1[g];
    }
    if (tid < Hdim) sWlin[tid] = Wlin[tid];
    const float bl = __ldg(blin);

    if (tid < Bsz) {                        // zero initial state (parity-0)
        g_h0p[0][cta * Bsz + tid] = 0ull;
        g_h1p[0][cta * Bsz + tid] = 0ull;
    }
    float c0 = 0.f, c1 = 0.f;               // distributed cell state

    // init barrier (line A)
    bar_arrive(&g_cntA);
    bar_wait(&g_cntA, 1u * NCTA);

    // ---- prologue: L0(0): h0p[0] -> h0p[1] ----
    {
        mv_l0(g_h0p[0], sW0, sRed, b2, ks, k0);
        float4 s = red_gather(sRed, ks, b2);
        float xv = g_xT[0 * Bsz + bown];
        float gi = s.x + fmaf(sWx[0*2 + jmu], xv, sB0[0*2 + jmu]);
        float gf = s.y + fmaf(sWx[1*2 + jmu], xv, sB0[1*2 + jmu]);
        float gg = s.z + fmaf(sWx[2*2 + jmu], xv, sB0[2*2 + jmu]);
        float go = s.w + fmaf(sWx[3*2 + jmu], xv, sB0[3*2 + jmu]);
        float cn = sigf(gf) * c0 + sigf(gi) * tanhf_(gg);
        c0 = cn;
        ((float*)g_h0p[1])[(cta * Bsz + bown) * 2 + jmu] = sigf(go) * tanhf_(cn);
        bar_arrive(&g_cntA);
        bar_wait(&g_cntA, 2u * NCTA);
    }

    for (int t = 0; t < Tlen; ++t) {
        const int pr = t & 1, nx = pr ^ 1;

        // ---- L1(t): h0p[nx] (new) + h1p[pr] -> h1p[nx] ----
        {
            mv_l1(g_h0p[nx], g_h1p[pr], sW1i, sW1h, sRed, b2, ks, k0);
            float4 s = red_gather(sRed, ks, b2);
            float gi = s.x + sB1[0*2 + jmu];
            float gf = s.y + sB1[1*2 + jmu];
            float gg = s.z + sB1[2*2 + jmu];
            float go = s.w + sB1[3*2 + jmu];
            float cn = sigf(gf) * c1 + sigf(gi) * tanhf_(gg);
            c1 = cn;
            ((float*)g_h1p[nx])[(cta * Bsz + bown) * 2 + jmu] = sigf(go) * tanhf_(cn);
        }
        bar_arrive(&g_cntB);                 // idB = t+1

        // ---- L0(t+1): h0p[nx] -> h0p[pr]  (hides B-barrier latency) ----
        if (t < Tlen - 1) {
            mv_l0(g_h0p[nx], sW0, sRed, b2, ks, k0);
            float4 s = red_gather(sRed, ks, b2);
            float xv = g_xT[(t + 1) * Bsz + bown];
            float gi = s.x + fmaf(sWx[0*2 + jmu], xv, sB0[0*2 + jmu]);
            float gf = s.y + fmaf(sWx[1*2 + jmu], xv, sB0[1*2 + jmu]);
            float gg = s.z + fmaf(sWx[2*2 + jmu], xv, sB0[2*2 + jmu]);
            float go = s.w + fmaf(sWx[3*2 + jmu], xv, sB0[3*2 + jmu]);
            float cn = sigf(gf) * c0 + sigf(gi) * tanhf_(gg);
            c0 = cn;
            ((float*)g_h0p[pr])[(cta * Bsz + bown) * 2 + jmu] = sigf(go) * tanhf_(cn);
            bar_arrive(&g_cntA);             // idA = t+3
        }

        // ---- wait for all h1(t), then output dot ----
        bar_wait(&g_cntB, (unsigned)(t + 1) * NCTA);
        {
            if (tid < 256) {
                const unsigned long long* __restrict__ hc = g_h1p[nx];
                int half = tid >> 7;         // 0..127 -> batch u0, 128..255 -> u0+1
                int kk   = tid & 127;
                int bb   = u0 + half;
                float2 hv = unpack2(__ldcg(hc + kk * Bsz + bb));
                float part = hv.x * sWlin[2*kk] + hv.y * sWlin[2*kk + 1];
                #pragma unroll
                for (int off = 16; off > 0; off >>= 1)
                    part += __shfl_down_sync(0xffffffffu, part, off);
                if ((tid & 31) == 0) sOut[tid >> 5] = part;
            }
            __syncthreads();
            if (tid == 0) {
                out[(u0 + 0) * Tlen + t] = sOut[0] + sOut[1] + sOut[2] + sOut[3] + bl;
                out[(u0 + 1) * Tlen + t] = sOut[4] + sOut[5] + sOut[6] + sOut[7] + bl;
            }
        }

        if (t < Tlen - 1)
            bar_wait(&g_cntA, (unsigned)(t + 3) * NCTA);   // h0(t+1) visible
    }

    // reset counters for next launch
    __syncthreads();
    if (tid == 0) {
        __threadfence();
        unsigned old = atomicAdd(&g_done, 1u);
        if (old == NCTA - 1) {
            atomicExch(&g_cntA, 0u);
            atomicExch(&g_cntB, 0u);
            atomicExch(&g_done, 0u);
        }
    }
}

extern "C" void kernel_launch(void* const* d_in, const int* in_sizes, int n_in,
                              void* d_out, int out_size) {
    (void)in_sizes; (void)n_in; (void)out_size;
    lstm_fused<<<NCTA, NTH>>>(
        (const float*)d_in[0],
        (const float*)d_in[1], (const float*)d_in[2],
        (const float*)d_in[3], (const float*)d_in[4],
        (const float*)d_in[5], (const float*)d_in[6],
        (const float*)d_in[7], (const float*)d_in[8],
        (const float*)d_in[9], (const float*)d_in[10],
        (float*)d_out);
}

// round 12
// speedup vs baseline: 2.2548x; 1.0720x over previous
#include <cuda_runtime.h>
#include <math.h>

#define NCTA 128
#define NTH  512
#define Bsz  256
#define Tlen 1024
#define Hdim 256
#define K2n  128   // Hdim/2 k-pairs (f32x2 lanes)
#define K2PT 32    // K2n / 4 k-split groups

// Persistent state, exchanged through L2 (double-buffered by step parity).
// u64 layout: [k2][b] packs {h[2k2][b], h[2k2+1][b]}.
// Parity p holds the pair (h0(t), h1(t-1)) for t with t&1 == p.
__device__ unsigned long long g_h0p[2][K2n * Bsz];
__device__ unsigned long long g_h1p[2][K2n * Bsz];
__device__ float g_xT[Tlen * Bsz];   // x transposed: [t][b]
__device__ unsigned g_cnt  = 0;      // single barrier line
__device__ unsigned g_done = 0;      // end-of-kernel reset rendezvous

union F2U { float2 f; unsigned long long u; };

__device__ __forceinline__ unsigned long long pack2(float a, float b) {
    F2U v; v.f.x = a; v.f.y = b; return v.u;
}
__device__ __forceinline__ float2 unpack2(unsigned long long u) {
    F2U v; v.u = u; return v.f;
}
// Blackwell packed fp32x2 FMA: 2 exact fp32 MACs per instruction.
__device__ __forceinline__ unsigned long long ffma2(unsigned long long a,
                                                    unsigned long long b,
                                                    unsigned long long c) {
    unsigned long long d;
    asm("fma.rn.f32x2 %0, %1, %2, %3;" : "=l"(d) : "l"(a), "l"(b), "l"(c));
    return d;
}
__device__ __forceinline__ float redsum(unsigned long long a) {
    F2U v; v.u = a; return v.f.x + v.f.y;
}
__device__ __forceinline__ float sigf(float x) {
    return __fdividef(1.0f, 1.0f + __expf(-x));
}
__device__ __forceinline__ float tanhf_(float x) {
    return fmaf(2.0f, sigf(2.0f * x), -1.0f);
}

// Split-phase grid barrier (NCTA co-resident CTAs, 1/SM).
__device__ __forceinline__ void bar_arrive(unsigned* c) {
    __syncthreads();                       // CTA's stores done
    if (threadIdx.x == 0) {
        asm volatile("red.release.gpu.global.add.u32 [%0], %1;"
                     :: "l"(c), "r"(1u) : "memory");
    }
}
__device__ __forceinline__ void bar_wait(unsigned* c, unsigned target) {
    if (threadIdx.x == 0) {
        unsigned v;
        do {
            asm volatile("ld.acquire.gpu.u32 %0, [%1];" : "=r"(v) : "l"(c));
        } while (v < target);
    }
    __syncthreads();
}

// ---- layer-0 matvec slice: partials into sRed rows [16..32) ----
__device__ __forceinline__ void mv_l0(const unsigned long long* __restrict__ hp,
                                      const ulonglong2* __restrict__ sW,
                                      float4* __restrict__ sRed,
                                      int b2, int ks, int k0) {
    unsigned long long aA[4][2], aB[4][2];
    #pragma unroll
    for (int q = 0; q < 4; ++q) { aA[q][0]=0ull; aA[q][1]=0ull; aB[q][0]=0ull; aB[q][1]=0ull; }
    #pragma unroll 16
    for (int i = 0; i < K2PT; ++i) {
        int k2 = k0 + i;
        unsigned long long hA = __ldcg(hp + k2 * Bsz + b2);
        unsigned long long hB = __ldcg(hp + k2 * Bsz + b2 + 128);
        #pragma unroll
        for (int q = 0; q < 4; ++q) {
            ulonglong2 w = sW[k2 * 4 + q];           // broadcast LDS.128
            aA[q][0] = ffma2(hA, w.x, aA[q][0]);
            aA[q][1] = ffma2(hA, w.y, aA[q][1]);
            aB[q][0] = ffma2(hB, w.x, aB[q][0]);
            aB[q][1] = ffma2(hB, w.y, aB[q][1]);
        }
    }
    #pragma unroll
    for (int jj = 0; jj < 2; ++jj) {
        sRed[(16 + ks*4 + jj*2 + 0)*128 + b2] =
            make_float4(redsum(aA[0][jj]), redsum(aA[1][jj]),
                        redsum(aA[2][jj]), redsum(aA[3][jj]));
        sRed[(16 + ks*4 + jj*2 + 1)*128 + b2] =
            make_float4(redsum(aB[0][jj]), redsum(aB[1][jj]),
                        redsum(aB[2][jj]), redsum(aB[3][jj]));
    }
}

// ---- layer-1 matvec slice (two inputs): partials into sRed rows [0..16) ----
__device__ __forceinline__ void mv_l1(const unsigned long long* __restrict__ ha,
                                      const unsigned long long* __restrict__ hb,
                                      const ulonglong2* __restrict__ sWi,
                                      const ulonglong2* __restrict__ sWh,
                                      float4* __restrict__ sRed,
                                      int b2, int ks, int k0) {
    unsigned long long aA[4][2], aB[4][2];
    #pragma unroll
    for (int q = 0; q < 4; ++q) { aA[q][0]=0ull; aA[q][1]=0ull; aB[q][0]=0ull; aB[q][1]=0ull; }
    #pragma unroll 8
    for (int i = 0; i < K2PT; ++i) {
        int k2 = k0 + i;
        unsigned long long vaA = __ldcg(ha + k2 * Bsz + b2);
        unsigned long long vaB = __ldcg(ha + k2 * Bsz + b2 + 128);
        unsigned long long vbA = __ldcg(hb + k2 * Bsz + b2);
        unsigned long long vbB = __ldcg(hb + k2 * Bsz + b2 + 128);
        #pragma unroll
        for (int q = 0; q < 4; ++q) {
            ulonglong2 wi = sWi[k2 * 4 + q];
            ulonglong2 wh = sWh[k2 * 4 + q];
            aA[q][0] = ffma2(vaA, wi.x, aA[q][0]);
            aA[q][1] = ffma2(vaA, wi.y, aA[q][1]);
            aB[q][0] = ffma2(vaB, wi.x, aB[q][0]);
            aB[q][1] = ffma2(vaB, wi.y, aB[q][1]);
            aA[q][0] = ffma2(vbA, wh.x, aA[q][0]);
            aA[q][1] = ffma2(vbA, wh.y, aA[q][1]);
            aB[q][0] = ffma2(vbB, wh.x, aB[q][0]);
            aB[q][1] = ffma2(vbB, wh.y, aB[q][1]);
        }
    }
    #pragma unroll
    for (int jj = 0; jj < 2; ++jj) {
        sRed[(ks*4 + jj*2 + 0)*128 + b2] =
            make_float4(redsum(aA[0][jj]), redsum(aA[1][jj]),
                        redsum(aA[2][jj]), redsum(aA[3][jj]));
        sRed[(ks*4 + jj*2 + 1)*128 + b2] =
            make_float4(redsum(aB[0][jj]), redsum(aB[1][jj]),
                        redsum(aB[2][jj]), redsum(aB[3][jj]));
    }
}

// gather this thread's (j,m) gate sums from the 4 k-group partials
__device__ __forceinline__ float4 red_gather(const float4* __restrict__ sRed,
                                             int base, int ks, int b2) {
    float4 s = sRed[(base + 0*4 + ks)*128 + b2];
    #pragma unroll
    for (int g = 1; g < 4; ++g) {
        float4 v = sRed[(base + g*4 + ks)*128 + b2];
        s.x += v.x; s.y += v.y; s.z += v.z; s.w += v.w;
    }
    return s;
}

__global__ void __launch_bounds__(NTH, 1)
lstm_fused(const float* __restrict__ x,
           const float* __restrict__ Wih0, const float* __restrict__ Whh0,
           const float* __restrict__ bih0, const float* __restrict__ bhh0,
           const float* __restrict__ Wih1, const float* __restrict__ Whh1,
           const float* __restrict__ bih1, const float* __restrict__ bhh1,
           const float* __restrict__ Wlin, const float* __restrict__ blin,
           float* __restrict__ out)
{
    __shared__ ulonglong2 sW0 [K2n * 4];   // 8 KB each, pair-packed
    __shared__ ulonglong2 sW1i[K2n * 4];
    __shared__ ulonglong2 sW1h[K2n * 4];
    __shared__ float4 sRed[32 * 128];      // 64 KB: rows [0,16) L1, [16,32) L0
    __shared__ float sWx[8], sB0[8], sB1[8];
    __shared__ float sWlin[Hdim];
    __shared__ float sOut[8];

    const int tid = threadIdx.x;
    const int b2  = tid & 127;
    const int ks  = tid >> 7;              // 0..3 (warp-uniform)
    const int cta = blockIdx.x;
    const int u0  = 2 * cta;
    const int jmu = ks >> 1;               // unit-in-pair this thread activates
    const int mmu = ks & 1;                // batch-half this thread activates
    const int bown = b2 + mmu * 128;       // owned batch index
    const int k0  = ks * K2PT;
    // output-gather role (tid < 256)
    const int okk = tid & 127;             // k2 index
    const int obb = u0 + (tid >> 7);       // batch {u0, u0+1}

    // ---- one-time staging ----
    for (int i = cta * NTH + tid; i < Bsz * Tlen; i += NCTA * NTH) {
        int b = i >> 10, t = i & (Tlen - 1);
        g_xT[t * Bsz + b] = x[i];
    }
    for (int e = tid; e < K2n * 4; e += NTH) {
        int k2 = e >> 2, q = e & 3;
        int base = (q * Hdim + u0) * Hdim + 2 * k2;
        sW0[e]  = make_ulonglong2(pack2(Whh0[base],        Whh0[base + 1]),
                                  pack2(Whh0[base + Hdim], Whh0[base + Hdim + 1]));
        sW1i[e] = make_ulonglong2(pack2(Wih1[base],        Wih1[base + 1]),
                                  pack2(Wih1[base + Hdim], Wih1[base + Hdim + 1]));
        sW1h[e] = make_ulonglong2(pack2(Whh1[base],        Whh1[base + 1]),
                                  pack2(Whh1[base + Hdim], Whh1[base + Hdim + 1]));
    }
    if (tid < 8) {
        int q = tid >> 1, j = tid & 1;
        int g = q * Hdim + u0 + j;
        sWx[tid] = Wih0[g];                // input dim == 1
        sB0[tid] = bih0[g] + bhh0[g];
        sB1[tid] = bih1[g] + bhh1[g];
    }
    if (tid < Hdim) sWlin[tid] = Wlin[tid];
    const float bl = __ldg(blin);

    if (tid < Bsz)                          // h1(-1) = 0 (parity-0)
        g_h1p[0][cta * Bsz + tid] = 0ull;
    float c0 = 0.f, c1 = 0.f;               // distributed cell state

    // barrier 1: staging + zeros visible
    bar_arrive(&g_cnt);
    bar_wait(&g_cnt, 1u * NCTA);

    // ---- prologue: h0(0) from zero state (no matvec needed) ----
    {
        float xv = g_xT[0 * Bsz + bown];
        float gi = fmaf(sWx[0*2 + jmu], xv, sB0[0*2 + jmu]);
        float gg = fmaf(sWx[2*2 + jmu], xv, sB0[2*2 + jmu]);
        float go = fmaf(sWx[3*2 + jmu], xv, sB0[3*2 + jmu]);
        float cn = sigf(gi) * tanhf_(gg);   // f-gate * 0 drops
        c0 = cn;
        ((float*)g_h0p[0])[(cta * Bsz + bown) * 2 + jmu] = sigf(go) * tanhf_(cn);
    }
    bar_arrive(&g_cnt);
    bar_wait(&g_cnt, 2u * NCTA);            // h0(0), h1(-1) all visible

    for (int t = 0; t < Tlen; ++t) {
        const int p = t & 1, nx = p ^ 1;

        // prefetch output operand for step t-1: h1(t-1) lives at parity p
        unsigned long long hv_pref = 0ull;
        if (tid < 256) hv_pref = __ldcg(&g_h1p[p][okk * Bsz + obb]);

        // ---- both matvecs, back-to-back (registers reused sequentially) ----
        mv_l1(g_h0p[p], g_h1p[p], sW1i, sW1h, sRed, b2, ks, k0);
        if (t < Tlen - 1)
            mv_l0(g_h0p[p], sW0, sRed, b2, ks, k0);
        __syncthreads();

        // ---- merged activations ----
        {   // layer 1: h1(t)
            float4 s = red_gather(sRed, 0, ks, b2);
            float gi = s.x + sB1[0*2 + jmu];
            float gf = s.y + sB1[1*2 + jmu];
            float gg = s.z + sB1[2*2 + jmu];
            float go = s.w + sB1[3*2 + jmu];
            float cn = sigf(gf) * c1 + sigf(gi) * tanhf_(gg);
            c1 = cn;
            ((float*)g_h1p[nx])[(cta * Bsz + bown) * 2 + jmu] = sigf(go) * tanhf_(cn);
        }
        if (t < Tlen - 1) {  // layer 0: h0(t+1)
            float4 s = red_gather(sRed, 16, ks, b2);
            float xv = g_xT[(t + 1) * Bsz + bown];
            float gi = s.x + fmaf(sWx[0*2 + jmu], xv, sB0[0*2 + jmu]);
            float gf = s.y + fmaf(sWx[1*2 + jmu], xv, sB0[1*2 + jmu]);
            float gg = s.z + fmaf(sWx[2*2 + jmu], xv, sB0[2*2 + jmu]);
            float go = s.w + fmaf(sWx[3*2 + jmu], xv, sB0[3*2 + jmu]);
            float cn = sigf(gf) * c0 + sigf(gi) * tanhf_(gg);
            c0 = cn;
            ((float*)g_h0p[nx])[(cta * Bsz + bown) * 2 + jmu] = sigf(go) * tanhf_(cn);
        }

        // ---- output(t-1) using prefetched h1(t-1) (before arrive: race-free) ----
        if (t >= 1) {
            if (tid < 256) {
                float2 hv = unpack2(hv_pref);
                float part = hv.x * sWlin[2*okk] + hv.y * sWlin[2*okk + 1];
                #pragma unroll
                for (int off = 16; off > 0; off >>= 1)
                    part += __shfl_down_sync(0xffffffffu, part, off);
                if ((tid & 31) == 0) sOut[tid >> 5] = part;
            }
            __syncthreads();
            if (tid == 0) {
                out[(u0 + 0) * Tlen + (t - 1)] = sOut[0] + sOut[1] + sOut[2] + sOut[3] + bl;
                out[(u0 + 1) * Tlen + (t - 1)] = sOut[4] + sOut[5] + sOut[6] + sOut[7] + bl;
            }
        }

        // ---- single barrier per step ----
        bar_arrive(&g_cnt);
        bar_wait(&g_cnt, (unsigned)(t + 3) * NCTA);
    }

    // ---- final output(1023): h1(1023) at parity 0 (t=1023 wrote nx=0) ----
    {
        if (tid < 256) {
            float2 hv = unpack2(__ldcg(&g_h1p[0][okk * Bsz + obb]));
            float part = hv.x * sWlin[2*okk] + hv.y * sWlin[2*okk + 1];
            #pragma unroll
            for (int off = 16; off > 0; off >>= 1)
                part += __shfl_down_sync(0xffffffffu, part, off);
            if ((tid & 31) == 0) sOut[tid >> 5] = part;
        }
        __syncthreads();
        if (tid == 0) {
            out[(u0 + 0) * Tlen + (Tlen - 1)] = sOut[0] + sOut[1] + sOut[2] + sOut[3] + bl;
            out[(u0 + 1) * Tlen + (Tlen - 1)] = sOut[4] + sOut[5] + sOut[6] + sOut[7] + bl;
        }
    }

    // reset counters for next launch
    __syncthreads();
    if (tid == 0) {
        __threadfence();
        unsigned old = atomicAdd(&g_done, 1u);
        if (old == NCTA - 1) {
            atomicExch(&g_cnt, 0u);
            atomicExch(&g_done, 0u);
        }
    }
}

extern "C" void kernel_launch(void* const* d_in, const int* in_sizes, int n_in,
                              void* d_out, int out_size) {
    (void)in_sizes; (void)n_in; (void)out_size;
    lstm_fused<<<NCTA, NTH>>>(
        (const float*)d_in[0],
        (const float*)d_in[1], (const float*)d_in[2],
        (const float*)d_in[3], (const float*)d_in[4],
        (const float*)d_in[5], (const float*)d_in[6],
        (const float*)d_in[7], (const float*)d_in[8],
        (const float*)d_in[9], (const float*)d_in[10],
        (float*)d_out);
}

// round 13
// speedup vs baseline: 2.3975x; 1.0633x over previous
#include <cuda_runtime.h>
#include <math.h>

#define NCTA 128
#define NTH  512
#define Bsz  256
#define Tlen 1024
#define Hdim 256
#define K2n  128   // Hdim/2 k-pairs (f32x2 lanes)
#define KQn  64    // Hdim/4 k-quads (LDG.128 units)
#define KQPT 16    // KQn / 4 k-split groups

// Persistent state, exchanged through L2 (double-buffered by step parity).
// ulonglong2 layout: [kq][b] packs {h[4kq..4kq+3][b]} as 4 floats.
// Parity p holds the pair (h0(t), h1(t-1)) for t with t&1 == p.
__device__ ulonglong2 g_h0q[2][KQn * Bsz];
__device__ ulonglong2 g_h1q[2][KQn * Bsz];
__device__ float g_xT[Tlen * Bsz];   // x transposed: [t][b]
__device__ unsigned g_cnt  = 0;      // single barrier line
__device__ unsigned g_done = 0;      // end-of-kernel reset rendezvous

union F2U { float2 f; unsigned long long u; };

__device__ __forceinline__ unsigned long long pack2(float a, float b) {
    F2U v; v.f.x = a; v.f.y = b; return v.u;
}
__device__ __forceinline__ float2 unpack2(unsigned long long u) {
    F2U v; v.u = u; return v.f;
}
// Blackwell packed fp32x2 FMA: 2 exact fp32 MACs per instruction.
__device__ __forceinline__ unsigned long long ffma2(unsigned long long a,
                                                    unsigned long long b,
                                                    unsigned long long c) {
    unsigned long long d;
    asm("fma.rn.f32x2 %0, %1, %2, %3;" : "=l"(d) : "l"(a), "l"(b), "l"(c));
    return d;
}
__device__ __forceinline__ float redsum(unsigned long long a) {
    F2U v; v.u = a; return v.f.x + v.f.y;
}
__device__ __forceinline__ float sigf(float x) {
    return __fdividef(1.0f, 1.0f + __expf(-x));
}
__device__ __forceinline__ float tanhf_(float x) {
    return fmaf(2.0f, sigf(2.0f * x), -1.0f);
}

// Split-phase grid barrier (NCTA co-resident CTAs, 1/SM).
__device__ __forceinline__ void bar_arrive(unsigned* c) {
    __syncthreads();                       // CTA's stores done
    if (threadIdx.x == 0) {
        asm volatile("red.release.gpu.global.add.u32 [%0], %1;"
                     :: "l"(c), "r"(1u) : "memory");
    }
}
__device__ __forceinline__ void bar_wait(unsigned* c, unsigned target) {
    if (threadIdx.x == 0) {
        unsigned v;
        do {
            asm volatile("ld.acquire.gpu.u32 %0, [%1];" : "=r"(v) : "l"(c));
        } while (v < target);
    }
    __syncthreads();
}

// ---- layer-0 matvec slice: partials into sRed rows [16..32) ----
__device__ __forceinline__ void mv_l0(const ulonglong2* __restrict__ hp,
                                      const ulonglong2* __restrict__ sW,
                                      float4* __restrict__ sRed,
                                      int b2, int ks, int kq0) {
    unsigned long long aA[4][2], aB[4][2];
    #pragma unroll
    for (int q = 0; q < 4; ++q) { aA[q][0]=0ull; aA[q][1]=0ull; aB[q][0]=0ull; aB[q][1]=0ull; }
    #pragma unroll 8
    for (int i = 0; i < KQPT; ++i) {
        int kq = kq0 + i;
        ulonglong2 hA = __ldcg(hp + kq * Bsz + b2);         // LDG.128: 2 k2-pairs
        ulonglong2 hB = __ldcg(hp + kq * Bsz + b2 + 128);
        int k2 = 2 * kq;
        #pragma unroll
        for (int q = 0; q < 4; ++q) {
            ulonglong2 w0 = sW[k2 * 4 + q];                 // broadcast LDS.128
            ulonglong2 w1 = sW[(k2 + 1) * 4 + q];
            aA[q][0] = ffma2(hA.x, w0.x, aA[q][0]);
            aA[q][1] = ffma2(hA.x, w0.y, aA[q][1]);
            aB[q][0] = ffma2(hB.x, w0.x, aB[q][0]);
            aB[q][1] = ffma2(hB.x, w0.y, aB[q][1]);
            aA[q][0] = ffma2(hA.y, w1.x, aA[q][0]);
            aA[q][1] = ffma2(hA.y, w1.y, aA[q][1]);
            aB[q][0] = ffma2(hB.y, w1.x, aB[q][0]);
            aB[q][1] = ffma2(hB.y, w1.y, aB[q][1]);
        }
    }
    #pragma unroll
    for (int jj = 0; jj < 2; ++jj) {
        sRed[(16 + ks*4 + jj*2 + 0)*128 + b2] =
            make_float4(redsum(aA[0][jj]), redsum(aA[1][jj]),
                        redsum(aA[2][jj]), redsum(aA[3][jj]));
        sRed[(16 + ks*4 + jj*2 + 1)*128 + b2] =
            make_float4(redsum(aB[0][jj]), redsum(aB[1][jj]),
                        redsum(aB[2][jj]), redsum(aB[3][jj]));
    }
}

// ---- layer-1 matvec slice (two inputs): partials into sRed rows [0..16) ----
__device__ __forceinline__ void mv_l1(const ulonglong2* __restrict__ ha,
                                      const ulonglong2* __restrict__ hb,
                                      const ulonglong2* __restrict__ sWi,
                                      const ulonglong2* __restrict__ sWh,
                                      float4* __restrict__ sRed,
                                      int b2, int ks, int kq0) {
    unsigned long long aA[4][2], aB[4][2];
    #pragma unroll
    for (int q = 0; q < 4; ++q) { aA[q][0]=0ull; aA[q][1]=0ull; aB[q][0]=0ull; aB[q][1]=0ull; }
    #pragma unroll 4
    for (int i = 0; i < KQPT; ++i) {
        int kq = kq0 + i;
        ulonglong2 vaA = __ldcg(ha + kq * Bsz + b2);
        ulonglong2 vaB = __ldcg(ha + kq * Bsz + b2 + 128);
        ulonglong2 vbA = __ldcg(hb + kq * Bsz + b2);
        ulonglong2 vbB = __ldcg(hb + kq * Bsz + b2 + 128);
        int k2 = 2 * kq;
        #pragma unroll
        for (int q = 0; q < 4; ++q) {
            ulonglong2 wi0 = sWi[k2 * 4 + q];
            ulonglong2 wi1 = sWi[(k2 + 1) * 4 + q];
            ulonglong2 wh0 = sWh[k2 * 4 + q];
            ulonglong2 wh1 = sWh[(k2 + 1) * 4 + q];
            aA[q][0] = ffma2(vaA.x, wi0.x, aA[q][0]);
            aA[q][1] = ffma2(vaA.x, wi0.y, aA[q][1]);
            aB[q][0] = ffma2(vaB.x, wi0.x, aB[q][0]);
            aB[q][1] = ffma2(vaB.x, wi0.y, aB[q][1]);
            aA[q][0] = ffma2(vaA.y, wi1.x, aA[q][0]);
            aA[q][1] = ffma2(vaA.y, wi1.y, aA[q][1]);
            aB[q][0] = ffma2(vaB.y, wi1.x, aB[q][0]);
            aB[q][1] = ffma2(vaB.y, wi1.y, aB[q][1]);
            aA[q][0] = ffma2(vbA.x, wh0.x, aA[q][0]);
            aA[q][1] = ffma2(vbA.x, wh0.y, aA[q][1]);
            aB[q][0] = ffma2(vbB.x, wh0.x, aB[q][0]);
            aB[q][1] = ffma2(vbB.x, wh0.y, aB[q][1]);
            aA[q][0] = ffma2(vbA.y, wh1.x, aA[q][0]);
            aA[q][1] = ffma2(vbA.y, wh1.y, aA[q][1]);
            aB[q][0] = ffma2(vbB.y, wh1.x, aB[q][0]);
            aB[q][1] = ffma2(vbB.y, wh1.y, aB[q][1]);
        }
    }
    #pragma unroll
    for (int jj = 0; jj < 2; ++jj) {
        sRed[(ks*4 + jj*2 + 0)*128 + b2] =
            make_float4(redsum(aA[0][jj]), redsum(aA[1][jj]),
                        redsum(aA[2][jj]), redsum(aA[3][jj]));
        sRed[(ks*4 + jj*2 + 1)*128 + b2] =
            make_float4(redsum(aB[0][jj]), redsum(aB[1][jj]),
                        redsum(aB[2][jj]), redsum(aB[3][jj]));
    }
}

// gather this thread's (j,m) gate sums from the 4 k-group partials
__device__ __forceinline__ float4 red_gather(const float4* __restrict__ sRed,
                                             int base, int ks, int b2) {
    float4 s = sRed[(base + 0*4 + ks)*128 + b2];
    #pragma unroll
    for (int g = 1; g < 4; ++g) {
        float4 v = sRed[(base + g*4 + ks)*128 + b2];
        s.x += v.x; s.y += v.y; s.z += v.z; s.w += v.w;
    }
    return s;
}

__global__ void __launch_bounds__(NTH, 1)
lstm_fused(const float* __restrict__ x,
           const float* __restrict__ Wih0, const float* __restrict__ Whh0,
           const float* __restrict__ bih0, const float* __restrict__ bhh0,
           const float* __restrict__ Wih1, const float* __restrict__ Whh1,
           const float* __restrict__ bih1, const float* __restrict__ bhh1,
           const float* __restrict__ Wlin, const float* __restrict__ blin,
           float* __restrict__ out)
{
    __shared__ ulonglong2 sW0 [K2n * 4];   // 8 KB each, pair-packed [k2*4+q]
    __shared__ ulonglong2 sW1i[K2n * 4];
    __shared__ ulonglong2 sW1h[K2n * 4];
    __shared__ float4 sRed[32 * 128];      // 64 KB: rows [0,16) L1, [16,32) L0
    __shared__ float sWx[8], sB0[8], sB1[8];
    __shared__ float4 sW4[KQn];            // Wlin as quads
    __shared__ float sOut[4];

    const int tid = threadIdx.x;
    const int b2  = tid & 127;
    const int ks  = tid >> 7;              // 0..3 (warp-uniform)
    const int cta = blockIdx.x;
    const int u0  = 2 * cta;
    const int jmu = ks >> 1;               // unit-in-pair this thread activates
    const int mmu = ks & 1;                // batch-half this thread activates
    const int bown = b2 + mmu * 128;       // owned batch index
    const int kq0 = ks * KQPT;
    // activation write target: unit u = u0 + jmu in quad layout
    const int wkq  = (u0 + jmu) >> 2;
    const int wslt = (u0 + jmu) & 3;
    // output-gather role (tid < 128): quad okq, batch obb
    const int okq = tid & 63;
    const int obb = u0 + ((tid >> 6) & 1);

    // ---- one-time staging ----
    for (int i = cta * NTH + tid; i < Bsz * Tlen; i += NCTA * NTH) {
        int b = i >> 10, t = i & (Tlen - 1);
        g_xT[t * Bsz + b] = x[i];
    }
    for (int e = tid; e < K2n * 4; e += NTH) {
        int k2 = e >> 2, q = e & 3;
        int base = (q * Hdim + u0) * Hdim + 2 * k2;
        sW0[e]  = make_ulonglong2(pack2(Whh0[base],        Whh0[base + 1]),
                                  pack2(Whh0[base + Hdim], Whh0[base + Hdim + 1]));
        sW1i[e] = make_ulonglong2(pack2(Wih1[base],        Wih1[base + 1]),
                                  pack2(Wih1[base + Hdim], Wih1[base + Hdim + 1]));
        sW1h[e] = make_ulonglong2(pack2(Whh1[base],        Whh1[base + 1]),
                                  pack2(Whh1[base + Hdim], Whh1[base + Hdim + 1]));
    }
    if (tid < 8) {
        int q = tid >> 1, j = tid & 1;
        int g = q * Hdim + u0 + j;
        sWx[tid] = Wih0[g];                // input dim == 1
        sB0[tid] = bih0[g] + bhh0[g];
        sB1[tid] = bih1[g] + bhh1[g];
    }
    if (tid < KQn) sW4[tid] = ((const float4*)Wlin)[tid];
    const float bl = __ldg(blin);

    if (tid < 128)                          // h1(-1) = 0 (parity-0), CTA's slice
        g_h1q[0][cta * 128 + tid] = make_ulonglong2(0ull, 0ull);
    float c0 = 0.f, c1 = 0.f;               // distributed cell state

    // barrier 1: staging + zeros visible
    bar_arrive(&g_cnt);
    bar_wait(&g_cnt, 1u * NCTA);

    // ---- prologue: h0(0) from zero state (no matvec needed) ----
    {
        float xv = g_xT[0 * Bsz + bown];
        float gi = fmaf(sWx[0*2 + jmu], xv, sB0[0*2 + jmu]);
        float gg = fmaf(sWx[2*2 + jmu], xv, sB0[2*2 + jmu]);
        float go = fmaf(sWx[3*2 + jmu], xv, sB0[3*2 + jmu]);
        float cn = sigf(gi) * tanhf_(gg);   // f-gate * 0 drops
        c0 = cn;
        ((float*)g_h0q[0])[(wkq * Bsz + bown) * 4 + wslt] = sigf(go) * tanhf_(cn);
    }
    bar_arrive(&g_cnt);
    bar_wait(&g_cnt, 2u * NCTA);            // h0(0), h1(-1) all visible

    for (int t = 0; t < Tlen; ++t) {
        const int p = t & 1, nx = p ^ 1;

        // prefetch output operand for step t-1: h1(t-1) lives at parity p
        ulonglong2 hv_pref = make_ulonglong2(0ull, 0ull);
        if (tid < 128) hv_pref = __ldcg(&g_h1q[p][okq * Bsz + obb]);

        // ---- both matvecs, back-to-back ----
        mv_l1(g_h0q[p], g_h1q[p], sW1i, sW1h, sRed, b2, ks, kq0);
        if (t < Tlen - 1)
            mv_l0(g_h0q[p], sW0, sRed, b2, ks, kq0);
        __syncthreads();

        // ---- merged activations ----
        {   // layer 1: h1(t)
            float4 s = red_gather(sRed, 0, ks, b2);
            float gi = s.x + sB1[0*2 + jmu];
            float gf = s.y + sB1[1*2 + jmu];
            float gg = s.z + sB1[2*2 + jmu];
            float go = s.w + sB1[3*2 + jmu];
            float cn = sigf(gf) * c1 + sigf(gi) * tanhf_(gg);
            c1 = cn;
            ((float*)g_h1q[nx])[(wkq * Bsz + bown) * 4 + wslt] = sigf(go) * tanhf_(cn);
        }
        if (t < Tlen - 1) {  // layer 0: h0(t+1)
            float4 s = red_gather(sRed, 16, ks, b2);
            float xv = g_xT[(t + 1) * Bsz + bown];
            float gi = s.x + fmaf(sWx[0*2 + jmu], xv, sB0[0*2 + jmu]);
            float gf = s.y + fmaf(sWx[1*2 + jmu], xv, sB0[1*2 + jmu]);
            float gg = s.z + fmaf(sWx[2*2 + jmu], xv, sB0[2*2 + jmu]);
            float go = s.w + fmaf(sWx[3*2 + jmu], xv, sB0[3*2 + jmu]);
            float cn = sigf(gf) * c0 + sigf(gi) * tanhf_(gg);
            c0 = cn;
            ((float*)g_h0q[nx])[(wkq * Bsz + bown) * 4 + wslt] = sigf(go) * tanhf_(cn);
        }

        // ---- arrive FIRST; output(t-1) executes inside the wait shadow ----
        bar_arrive(&g_cnt);

        if (t >= 1) {
            if (tid < 128) {
                float2 lo = unpack2(hv_pref.x), hi = unpack2(hv_pref.y);
                float4 wl = sW4[okq];
                float part = lo.x * wl.x + lo.y * wl.y + hi.x * wl.z + hi.y * wl.w;
                #pragma unroll
                for (int off = 16; off > 0; off >>= 1)
                    part += __shfl_down_sync(0xffffffffu, part, off);
                if ((tid & 31) == 0) sOut[tid >> 5] = part;
            }
            __syncthreads();
            if (tid == 0) {
                out[(u0 + 0) * Tlen + (t - 1)] = sOut[0] + sOut[1] + bl;
                out[(u0 + 1) * Tlen + (t - 1)] = sOut[2] + sOut[3] + bl;
            }
        }

        bar_wait(&g_cnt, (unsigned)(t + 3) * NCTA);
    }

    // ---- final output(1023): h1(1023) at parity 0 ----
    {
        if (tid < 128) {
            ulonglong2 hv = __ldcg(&g_h1q[0][okq * Bsz + obb]);
            float2 lo = unpack2(hv.x), hi = unpack2(hv.y);
            float4 wl = sW4[okq];
            float part = lo.x * wl.x + lo.y * wl.y + hi.x * wl.z + hi.y * wl.w;
            #pragma unroll
            for (int off = 16; off > 0; off >>= 1)
                part += __shfl_down_sync(0xffffffffu, part, off);
            if ((tid & 31) == 0) sOut[tid >> 5] = part;
        }
        __syncthreads();
        if (tid == 0) {
            out[(u0 + 0) * Tlen + (Tlen - 1)] = sOut[0] + sOut[1] + bl;
            out[(u0 + 1) * Tlen + (Tlen - 1)] = sOut[2] + sOut[3] + bl;
        }
    }

    // reset counters for next launch
    __syncthreads();
    if (tid == 0) {
        __threadfence();
        unsigned old = atomicAdd(&g_done, 1u);
        if (old == NCTA - 1) {
            atomicExch(&g_cnt, 0u);
            atomicExch(&g_done, 0u);
        }
    }
}

extern "C" void kernel_launch(void* const* d_in, const int* in_sizes, int n_in,
                              void* d_out, int out_size) {
    (void)in_sizes; (void)n_in; (void)out_size;
    lstm_fused<<<NCTA, NTH>>>(
        (const float*)d_in[0],
        (const float*)d_in[1], (const float*)d_in[2],
        (const float*)d_in[3], (const float*)d_in[4],
        (const float*)d_in[5], (const float*)d_in[6],
        (const float*)d_in[7], (const float*)d_in[8],
        (const float*)d_in[9], (const float*)d_in[10],
        (float*)d_out);
}